// round 1
// baseline (speedup 1.0000x reference)
#include <cuda_runtime.h>
#include <math.h>

#define SEQ  2048
#define DM   4096
#define NH   16
#define DH   256
#define DFF  16384

#define BM 128
#define BN 128
#define BK 32

// ---------------- scratch (device globals: no allocs allowed) ----------------
__device__ float g_xn[(size_t)SEQ * DM];
__device__ float g_q [(size_t)SEQ * DM];
__device__ float g_k [(size_t)SEQ * DM];
__device__ float g_v [(size_t)SEQ * DM];
__device__ float g_av[(size_t)SEQ * DM];
__device__ float g_ao[(size_t)SEQ * DM];
__device__ float g_f1[(size_t)SEQ * DFF];
__device__ float g_sc[(size_t)NH * SEQ * SEQ];

// ---------------- helpers ----------------
__device__ __forceinline__ unsigned f2tf(float x) {
    unsigned r;
    asm("cvt.rna.tf32.f32 %0, %1;" : "=r"(r) : "f"(x));
    return r;
}

__device__ __forceinline__ float gelu_f(float x) {
    float t = tanhf(0.7978845608028654f * (x + 0.044715f * x * x * x));
    return 0.5f * x * (1.0f + t);
}

__device__ __forceinline__ void mma_tf32(float c[4], const unsigned a[4], const unsigned b[2]) {
    asm volatile(
        "mma.sync.aligned.m16n8k8.row.col.f32.tf32.tf32.f32 "
        "{%0,%1,%2,%3},{%4,%5,%6,%7},{%8,%9},{%0,%1,%2,%3};"
        : "+f"(c[0]), "+f"(c[1]), "+f"(c[2]), "+f"(c[3])
        : "r"(a[0]), "r"(a[1]), "r"(a[2]), "r"(a[3]), "r"(b[0]), "r"(b[1]));
}

// ---------------- layernorm ----------------
__global__ void ln_kernel(const float* __restrict__ x, const float* __restrict__ sc,
                          const float* __restrict__ of, float* __restrict__ xn) {
    int row = blockIdx.x;
    const float* xr = x + (size_t)row * DM;
    float* xo = xn + (size_t)row * DM;
    __shared__ float red[256];
    int tid = threadIdx.x;

    float s = 0.f;
    for (int j = tid; j < DM; j += 256) s += xr[j];
    red[tid] = s; __syncthreads();
    for (int st = 128; st > 0; st >>= 1) { if (tid < st) red[tid] += red[tid + st]; __syncthreads(); }
    float mean = red[0] * (1.0f / DM);
    __syncthreads();

    float v = 0.f;
    for (int j = tid; j < DM; j += 256) { float d = xr[j] - mean; v += d * d; }
    red[tid] = v; __syncthreads();
    for (int st = 128; st > 0; st >>= 1) { if (tid < st) red[tid] += red[tid + st]; __syncthreads(); }
    float rstd = rsqrtf(red[0] * (1.0f / DM) + 1e-5f);

    for (int j = tid; j < DM; j += 256) xo[j] = sc[j] * rstd * (xr[j] - mean) + of[j];
}

// ---------------- RoPE (q,k first 64 dims of each head) ----------------
__global__ void rope_kernel(float* __restrict__ q, float* __restrict__ k) {
    int t = blockIdx.x, tid = threadIdx.x;
    __shared__ float ss[32], cc[32];
    if (tid < 32) {
        double inv = pow(10000.0, -((double)(2 * tid)) / 64.0);
        double a = (double)t * inv;
        ss[tid] = (float)sin(a);
        cc[tid] = (float)cos(a);
    }
    __syncthreads();
    int head = tid >> 5, i = tid & 31;
    size_t off = (size_t)t * DM + head * DH + 2 * i;
    float s = ss[i], co = cc[i];
    float q0 = q[off], q1 = q[off + 1];
    q[off]     = q0 * co - q1 * s;
    q[off + 1] = q1 * co + q0 * s;
    float k0 = k[off], k1 = k[off + 1];
    k[off]     = k0 * co - k1 * s;
    k[off + 1] = k1 * co + k0 * s;
}

// ---------------- generic TF32 GEMM ----------------
// EPI: 0 = C=acc; 1 = acc+bias; 2 = gelu(acc+bias); 3 = acc+bias+addend
template <int EPI>
__global__ __launch_bounds__(256)
void gemm_tf32(const float* __restrict__ A, const float* __restrict__ B,
               float* __restrict__ C,
               int M, int N, int K, int lda, int ldb, int ldc,
               long sAz, long sBz, long sCz,
               const float* __restrict__ bias,
               const float* __restrict__ addend,
               int causal) {
    A += (size_t)blockIdx.z * sAz;
    B += (size_t)blockIdx.z * sBz;
    C += (size_t)blockIdx.z * sCz;
    int m0 = blockIdx.y * BM, n0 = blockIdx.x * BN;
    int tid = threadIdx.x;

    __shared__ unsigned As[BM][BK + 4];
    __shared__ unsigned Bs[BK][BN + 8];

    int kend = causal ? ((m0 + BM < K) ? (m0 + BM) : K) : K;
    int warp = tid >> 5, lane = tid & 31;
    int wm = (warp & 3) * 32, wn = (warp >> 2) * 64;
    int r = lane >> 2, c = lane & 3;

    float acc[2][8][4];
#pragma unroll
    for (int i = 0; i < 2; i++)
#pragma unroll
        for (int j = 0; j < 8; j++)
#pragma unroll
            for (int q = 0; q < 4; q++) acc[i][j][q] = 0.f;

    int ak = (tid & 7) * 4;
    int bn = (tid & 31) * 4;

    for (int k0 = 0; k0 < kend; k0 += BK) {
#pragma unroll
        for (int i = 0; i < 4; i++) {
            int m = (tid >> 3) + i * 32;
            const float4 v = *(const float4*)(A + (size_t)(m0 + m) * lda + k0 + ak);
            As[m][ak + 0] = f2tf(v.x); As[m][ak + 1] = f2tf(v.y);
            As[m][ak + 2] = f2tf(v.z); As[m][ak + 3] = f2tf(v.w);
        }
#pragma unroll
        for (int i = 0; i < 4; i++) {
            int kr = (tid >> 5) + i * 8;
            const float4 v = *(const float4*)(B + (size_t)(k0 + kr) * ldb + n0 + bn);
            Bs[kr][bn + 0] = f2tf(v.x); Bs[kr][bn + 1] = f2tf(v.y);
            Bs[kr][bn + 2] = f2tf(v.z); Bs[kr][bn + 3] = f2tf(v.w);
        }
        __syncthreads();
#pragma unroll
        for (int ks = 0; ks < BK / 8; ks++) {
            unsigned a[2][4], b[8][2];
#pragma unroll
            for (int mt = 0; mt < 2; mt++) {
                a[mt][0] = As[wm + mt * 16 + r    ][ks * 8 + c];
                a[mt][1] = As[wm + mt * 16 + r + 8][ks * 8 + c];
                a[mt][2] = As[wm + mt * 16 + r    ][ks * 8 + c + 4];
                a[mt][3] = As[wm + mt * 16 + r + 8][ks * 8 + c + 4];
            }
#pragma unroll
            for (int nt = 0; nt < 8; nt++) {
                b[nt][0] = Bs[ks * 8 + c    ][wn + nt * 8 + r];
                b[nt][1] = Bs[ks * 8 + c + 4][wn + nt * 8 + r];
            }
#pragma unroll
            for (int mt = 0; mt < 2; mt++)
#pragma unroll
                for (int nt = 0; nt < 8; nt++) mma_tf32(acc[mt][nt], a[mt], b[nt]);
        }
        __syncthreads();
    }

#pragma unroll
    for (int mt = 0; mt < 2; mt++)
#pragma unroll
        for (int nt = 0; nt < 8; nt++) {
            int gm0 = m0 + wm + mt * 16 + r;
            int gn = n0 + wn + nt * 8 + 2 * c;
#pragma unroll
            for (int h = 0; h < 2; h++) {
                int gm = gm0 + h * 8;
                float2 val;
                val.x = acc[mt][nt][h * 2];
                val.y = acc[mt][nt][h * 2 + 1];
                if (EPI == 1 || EPI == 2 || EPI == 3) { val.x += bias[gn]; val.y += bias[gn + 1]; }
                if (EPI == 2) { val.x = gelu_f(val.x); val.y = gelu_f(val.y); }
                if (EPI == 3) {
                    const float2 ad = *(const float2*)(addend + (size_t)gm * ldc + gn);
                    val.x += ad.x; val.y += ad.y;
                }
                *(float2*)(C + (size_t)gm * ldc + gn) = val;
            }
        }
}

// ---------------- scores: logits[h] = q_h k_h^T / 16 + attn_bias + causal ----------------
__global__ __launch_bounds__(256)
void scores_kernel(const float* __restrict__ q, const float* __restrict__ k,
                   const float* __restrict__ ab, float* __restrict__ sc) {
    int h = blockIdx.z;
    int m0 = blockIdx.y * BM, n0 = blockIdx.x * BN;
    float* out = sc + ((size_t)h << 22);  // h * 2048 * 2048
    int tid = threadIdx.x;

    if (n0 > m0 + BM - 1) {  // fully masked block: exp() underflows to 0 either way
        for (int e = tid; e < BM * BN; e += 256) {
            int m = e >> 7, n = e & 127;
            size_t idx = (size_t)(m0 + m) * SEQ + (n0 + n);
            out[idx] = ab[idx] - 1e10f;
        }
        return;
    }

    __shared__ unsigned As[BM][BK + 4];
    __shared__ unsigned Bs[BK][BN + 8];
    int warp = tid >> 5, lane = tid & 31;
    int wm = (warp & 3) * 32, wn = (warp >> 2) * 64;
    int r = lane >> 2, c = lane & 3;

    float acc[2][8][4];
#pragma unroll
    for (int i = 0; i < 2; i++)
#pragma unroll
        for (int j = 0; j < 8; j++)
#pragma unroll
            for (int qq = 0; qq < 4; qq++) acc[i][j][qq] = 0.f;

    const float* Aq = q + (size_t)h * DH;
    const float* Bk = k + (size_t)h * DH;
    int ak = (tid & 7) * 4;

    for (int k0 = 0; k0 < DH; k0 += BK) {
#pragma unroll
        for (int i = 0; i < 4; i++) {
            int m = (tid >> 3) + i * 32;
            const float4 v = *(const float4*)(Aq + (size_t)(m0 + m) * DM + k0 + ak);
            As[m][ak + 0] = f2tf(v.x); As[m][ak + 1] = f2tf(v.y);
            As[m][ak + 2] = f2tf(v.z); As[m][ak + 3] = f2tf(v.w);
        }
#pragma unroll
        for (int i = 0; i < 4; i++) {
            int j = tid & 127;
            int kq = (tid >> 7) + i * 2;  // 0..7
            const float4 v = *(const float4*)(Bk + (size_t)(n0 + j) * DM + k0 + kq * 4);
            Bs[kq * 4 + 0][j] = f2tf(v.x); Bs[kq * 4 + 1][j] = f2tf(v.y);
            Bs[kq * 4 + 2][j] = f2tf(v.z); Bs[kq * 4 + 3][j] = f2tf(v.w);
        }
        __syncthreads();
#pragma unroll
        for (int ks = 0; ks < BK / 8; ks++) {
            unsigned a[2][4], b[8][2];
#pragma unroll
            for (int mt = 0; mt < 2; mt++) {
                a[mt][0] = As[wm + mt * 16 + r    ][ks * 8 + c];
                a[mt][1] = As[wm + mt * 16 + r + 8][ks * 8 + c];
                a[mt][2] = As[wm + mt * 16 + r    ][ks * 8 + c + 4];
                a[mt][3] = As[wm + mt * 16 + r + 8][ks * 8 + c + 4];
            }
#pragma unroll
            for (int nt = 0; nt < 8; nt++) {
                b[nt][0] = Bs[ks * 8 + c    ][wn + nt * 8 + r];
                b[nt][1] = Bs[ks * 8 + c + 4][wn + nt * 8 + r];
            }
#pragma unroll
            for (int mt = 0; mt < 2; mt++)
#pragma unroll
                for (int nt = 0; nt < 8; nt++) mma_tf32(acc[mt][nt], a[mt], b[nt]);
        }
        __syncthreads();
    }

    const float scale = 1.0f / 16.0f;  // 1/sqrt(256)
#pragma unroll
    for (int mt = 0; mt < 2; mt++)
#pragma unroll
        for (int nt = 0; nt < 8; nt++) {
            int gm0 = m0 + wm + mt * 16 + r;
            int gn = n0 + wn + nt * 8 + 2 * c;
#pragma unroll
            for (int hh = 0; hh < 2; hh++) {
                int gm = gm0 + hh * 8;
                size_t base = (size_t)gm * SEQ + gn;
                float v0 = acc[mt][nt][hh * 2]     * scale + ab[base]     + ((gn     > gm) ? -1e10f : 0.f);
                float v1 = acc[mt][nt][hh * 2 + 1] * scale + ab[base + 1] + ((gn + 1 > gm) ? -1e10f : 0.f);
                out[base] = v0;
                out[base + 1] = v1;
            }
        }
}

// ---------------- softmax over last dim ----------------
__global__ void softmax_kernel(float* __restrict__ sc) {
    size_t row = blockIdx.x;
    float* p = sc + row * SEQ;
    __shared__ float red[256];
    int tid = threadIdx.x;

    float vals[8];
    float m = -3.4e38f;
#pragma unroll
    for (int i = 0; i < 8; i++) { vals[i] = p[tid + i * 256]; m = fmaxf(m, vals[i]); }
    red[tid] = m; __syncthreads();
    for (int s = 128; s > 0; s >>= 1) { if (tid < s) red[tid] = fmaxf(red[tid], red[tid + s]); __syncthreads(); }
    m = red[0]; __syncthreads();

    float sum = 0.f;
#pragma unroll
    for (int i = 0; i < 8; i++) { vals[i] = expf(vals[i] - m); sum += vals[i]; }
    red[tid] = sum; __syncthreads();
    for (int s = 128; s > 0; s >>= 1) { if (tid < s) red[tid] += red[tid + s]; __syncthreads(); }
    float inv = 1.0f / red[0];
#pragma unroll
    for (int i = 0; i < 8; i++) p[tid + i * 256] = vals[i] * inv;
}

// ---------------- launch ----------------
extern "C" void kernel_launch(void* const* d_in, const int* in_sizes, int n_in,
                              void* d_out, int out_size) {
    const float* x   = (const float*)d_in[0];
    const float* ab  = (const float*)d_in[1];
    const float* lns = (const float*)d_in[2];
    const float* lno = (const float*)d_in[3];
    const float* wq  = (const float*)d_in[4];
    const float* wk  = (const float*)d_in[5];
    const float* wv  = (const float*)d_in[6];
    const float* wo  = (const float*)d_in[7];
    const float* w1  = (const float*)d_in[8];
    const float* b1  = (const float*)d_in[9];
    const float* w2  = (const float*)d_in[10];
    const float* b2  = (const float*)d_in[11];
    float* out = (float*)d_out;

    float *xn, *q, *k, *v, *av, *ao, *f1, *scr;
    cudaGetSymbolAddress((void**)&xn,  g_xn);
    cudaGetSymbolAddress((void**)&q,   g_q);
    cudaGetSymbolAddress((void**)&k,   g_k);
    cudaGetSymbolAddress((void**)&v,   g_v);
    cudaGetSymbolAddress((void**)&av,  g_av);
    cudaGetSymbolAddress((void**)&ao,  g_ao);
    cudaGetSymbolAddress((void**)&f1,  g_f1);
    cudaGetSymbolAddress((void**)&scr, g_sc);

    // 1. LayerNorm
    ln_kernel<<<SEQ, 256>>>(x, lns, lno, xn);

    // 2. QKV projections
    dim3 g1(DM / BN, SEQ / BM);
    gemm_tf32<0><<<g1, 256>>>(xn, wq, q, SEQ, DM, DM, DM, DM, DM, 0, 0, 0, nullptr, nullptr, 0);
    gemm_tf32<0><<<g1, 256>>>(xn, wk, k, SEQ, DM, DM, DM, DM, DM, 0, 0, 0, nullptr, nullptr, 0);
    gemm_tf32<0><<<g1, 256>>>(xn, wv, v, SEQ, DM, DM, DM, DM, DM, 0, 0, 0, nullptr, nullptr, 0);

    // 3. RoPE
    rope_kernel<<<SEQ, 512>>>(q, k);

    // 4. logits + mask + bias
    dim3 gs(SEQ / BN, SEQ / BM, NH);
    scores_kernel<<<gs, 256>>>(q, k, ab, scr);

    // 5. softmax
    softmax_kernel<<<NH * SEQ, 256>>>(scr);

    // 6. attn_vec = weights @ v  (causal K-bound)
    dim3 gav(DH / BN, SEQ / BM, NH);
    gemm_tf32<0><<<gav, 256>>>(scr, v, av, SEQ, DH, SEQ, SEQ, DM, DM,
                               (long)SEQ * SEQ, (long)DH, (long)DH, nullptr, nullptr, 1);

    // 7. attn_out = attn_vec @ wo
    gemm_tf32<0><<<g1, 256>>>(av, wo, ao, SEQ, DM, DM, DM, DM, DM, 0, 0, 0, nullptr, nullptr, 0);

    // 8. ffn hidden = gelu(xn @ w1 + b1)
    dim3 gf1(DFF / BN, SEQ / BM);
    gemm_tf32<2><<<gf1, 256>>>(xn, w1, f1, SEQ, DFF, DM, DM, DFF, DFF, 0, 0, 0, b1, nullptr, 0);

    // 9. out = f1 @ w2 + b2 + attn_out
    gemm_tf32<3><<<g1, 256>>>(f1, w2, out, SEQ, DM, DFF, DFF, DM, DM, 0, 0, 0, b2, ao, 0);
}

// round 2
// speedup vs baseline: 1.1218x; 1.1218x over previous
#include <cuda_runtime.h>
#include <math.h>

#define SEQ  2048
#define DM   4096
#define NH   16
#define DH   256
#define DFF  16384

#define BM 128
#define BN 128
#define BK 32
#define STAGES 3

#define APAD 4
#define BPAD 8
#define ALD (BK + APAD)    // 36 words per A row
#define BLD (BN + BPAD)    // 136 words per B row
#define A_STAGE_W (BM * ALD)       // 4608 words
#define B_STAGE_W (BK * BLD)       // 4352 words
#define S_STAGE_W (BM * ALD)       // scores B tile (n-major), 4608 words

// ---------------- scratch (device globals; allocation is forbidden) ----------------
__device__ float g_xn[(size_t)SEQ * DM];
__device__ float g_q [(size_t)SEQ * DM];
__device__ float g_k [(size_t)SEQ * DM];
__device__ float g_v [(size_t)SEQ * DM];
__device__ float g_av[(size_t)SEQ * DM];
__device__ float g_ao[(size_t)SEQ * DM];
__device__ float g_f1[(size_t)SEQ * DFF];
__device__ float g_sc[(size_t)NH * SEQ * SEQ];
// tf32-rounded weights
__device__ float g_rwq[(size_t)DM * DM];
__device__ float g_rwk[(size_t)DM * DM];
__device__ float g_rwv[(size_t)DM * DM];
__device__ float g_rwo[(size_t)DM * DM];
__device__ float g_rw1[(size_t)DM * DFF];
__device__ float g_rw2[(size_t)DFF * DM];

// ---------------- helpers ----------------
__device__ __forceinline__ unsigned f2tf(float x) {
    unsigned r;
    asm("cvt.rna.tf32.f32 %0, %1;" : "=r"(r) : "f"(x));
    return r;
}
__device__ __forceinline__ float rnd_tf32(float x) { return __uint_as_float(f2tf(x)); }

__device__ __forceinline__ float gelu_f(float x) {
    float t = tanhf(0.7978845608028654f * (x + 0.044715f * x * x * x));
    return 0.5f * x * (1.0f + t);
}

__device__ __forceinline__ void mma_tf32(float c[4], const unsigned a[4], const unsigned b[2]) {
    asm volatile(
        "mma.sync.aligned.m16n8k8.row.col.f32.tf32.tf32.f32 "
        "{%0,%1,%2,%3},{%4,%5,%6,%7},{%8,%9},{%0,%1,%2,%3};"
        : "+f"(c[0]), "+f"(c[1]), "+f"(c[2]), "+f"(c[3])
        : "r"(a[0]), "r"(a[1]), "r"(a[2]), "r"(a[3]), "r"(b[0]), "r"(b[1]));
}

#define CP_A16(saddr, gptr) \
    asm volatile("cp.async.cg.shared.global [%0], [%1], 16;\n" :: "r"(saddr), "l"(gptr))
#define CP_COMMIT() asm volatile("cp.async.commit_group;\n" ::: "memory")
#define CP_WAIT1()  asm volatile("cp.async.wait_group 1;\n" ::: "memory")

__device__ __forceinline__ unsigned smem_u32(const void* p) {
    return (unsigned)__cvta_generic_to_shared(p);
}

// ---------------- rounding pass (weights -> tf32 bit patterns) ----------------
__global__ void round_kernel(const float4* __restrict__ src, float4* __restrict__ dst, size_t n4) {
    size_t i = (size_t)blockIdx.x * blockDim.x + threadIdx.x;
    size_t stride = (size_t)gridDim.x * blockDim.x;
    for (; i < n4; i += stride) {
        float4 v = src[i];
        v.x = rnd_tf32(v.x); v.y = rnd_tf32(v.y);
        v.z = rnd_tf32(v.z); v.w = rnd_tf32(v.w);
        dst[i] = v;
    }
}

// ---------------- layernorm (stores tf32-rounded xn) ----------------
__global__ void ln_kernel(const float* __restrict__ x, const float* __restrict__ sc,
                          const float* __restrict__ of, float* __restrict__ xn) {
    int row = blockIdx.x;
    const float* xr = x + (size_t)row * DM;
    float* xo = xn + (size_t)row * DM;
    __shared__ float red[256];
    int tid = threadIdx.x;

    float s = 0.f;
    for (int j = tid; j < DM; j += 256) s += xr[j];
    red[tid] = s; __syncthreads();
    for (int st = 128; st > 0; st >>= 1) { if (tid < st) red[tid] += red[tid + st]; __syncthreads(); }
    float mean = red[0] * (1.0f / DM);
    __syncthreads();

    float v = 0.f;
    for (int j = tid; j < DM; j += 256) { float d = xr[j] - mean; v += d * d; }
    red[tid] = v; __syncthreads();
    for (int st = 128; st > 0; st >>= 1) { if (tid < st) red[tid] += red[tid + st]; __syncthreads(); }
    float rstd = rsqrtf(red[0] * (1.0f / DM) + 1e-5f);

    for (int j = tid; j < DM; j += 256)
        xo[j] = rnd_tf32(sc[j] * rstd * (xr[j] - mean) + of[j]);
}

// ---------------- RoPE + full-row tf32 rounding of q,k ----------------
__global__ void rope_kernel(float* __restrict__ q, float* __restrict__ k) {
    int t = blockIdx.x, tid = threadIdx.x;
    __shared__ float ss[32], cc[32];
    if (tid < 32) {
        double inv = pow(10000.0, -((double)(2 * tid)) / 64.0);
        double a = (double)t * inv;
        ss[tid] = (float)sin(a);
        cc[tid] = (float)cos(a);
    }
    __syncthreads();
    int head = tid >> 5, i = tid & 31;
    size_t off = (size_t)t * DM + head * DH + 2 * i;
    float s = ss[i], co = cc[i];
    float q0 = q[off], q1 = q[off + 1];
    q[off]     = rnd_tf32(q0 * co - q1 * s);
    q[off + 1] = rnd_tf32(q1 * co + q0 * s);
    float k0 = k[off], k1 = k[off + 1];
    k[off]     = rnd_tf32(k0 * co - k1 * s);
    k[off + 1] = rnd_tf32(k1 * co + k0 * s);
    // round pass-through dims [64, 256)
    size_t base = (size_t)t * DM + head * DH;
#pragma unroll
    for (int sgi = 0; sgi < 6; sgi++) {
        size_t j = base + 64 + i + sgi * 32;
        q[j] = rnd_tf32(q[j]);
        k[j] = rnd_tf32(k[j]);
    }
}

// ---------------- pipelined TF32 GEMM (B is K-major [k][n]) ----------------
// EPI: 0=C=acc; 2=gelu(acc+bias); 3=acc+bias+addend.  ROUND: tf32-round output.
template <int EPI, int ROUND>
__global__ __launch_bounds__(256)
void gemm_pipe(const float* __restrict__ A, const float* __restrict__ B,
               float* __restrict__ C,
               int K, int lda, int ldb, int ldc,
               long sAz, long sBz, long sCz,
               const float* __restrict__ bias,
               const float* __restrict__ addend,
               int causal) {
    extern __shared__ float sm[];
    float* Asm = sm;
    float* Bsm = sm + STAGES * A_STAGE_W;

    A += (size_t)blockIdx.z * sAz;
    B += (size_t)blockIdx.z * sBz;
    C += (size_t)blockIdx.z * sCz;
    int m0 = blockIdx.y * BM, n0 = blockIdx.x * BN;
    int tid = threadIdx.x;
    int kend = causal ? ((m0 + BM < K) ? (m0 + BM) : K) : K;
    int nk = kend / BK;

    const float* Ag = A + (size_t)(m0 + (tid >> 3)) * lda + (tid & 7) * 4;
    const float* Bg = B + (size_t)(tid >> 5) * ldb + n0 + (tid & 31) * 4;
    unsigned sA0 = smem_u32(Asm) + ((tid >> 3) * ALD + (tid & 7) * 4) * 4;
    unsigned sB0 = smem_u32(Bsm) + ((tid >> 5) * BLD + (tid & 31) * 4) * 4;

    auto issue = [&](int t) {
        int st = t % STAGES;
        int k0 = t * BK;
        unsigned a = sA0 + st * (A_STAGE_W * 4);
        unsigned b = sB0 + st * (B_STAGE_W * 4);
#pragma unroll
        for (int i = 0; i < 4; i++)
            CP_A16(a + i * 32 * ALD * 4, Ag + (size_t)i * 32 * lda + k0);
#pragma unroll
        for (int i = 0; i < 4; i++)
            CP_A16(b + i * 8 * BLD * 4, Bg + (size_t)(k0 + i * 8) * ldb);
    };

    issue(0); CP_COMMIT();
    if (nk > 1) issue(1);
    CP_COMMIT();

    int warp = tid >> 5, lane = tid & 31;
    int wm = (warp & 3) * 32, wn = (warp >> 2) * 64;
    int r = lane >> 2, c = lane & 3;

    float acc[2][8][4];
#pragma unroll
    for (int i = 0; i < 2; i++)
#pragma unroll
        for (int j = 0; j < 8; j++)
#pragma unroll
            for (int qq = 0; qq < 4; qq++) acc[i][j][qq] = 0.f;

    for (int t = 0; t < nk; t++) {
        CP_WAIT1();
        __syncthreads();
        if (t + 2 < nk) issue(t + 2);
        CP_COMMIT();

        const unsigned* Au = reinterpret_cast<const unsigned*>(Asm + (t % STAGES) * A_STAGE_W);
        const unsigned* Bu = reinterpret_cast<const unsigned*>(Bsm + (t % STAGES) * B_STAGE_W);
#pragma unroll
        for (int ks = 0; ks < BK / 8; ks++) {
            unsigned a[2][4], b[8][2];
#pragma unroll
            for (int mt = 0; mt < 2; mt++) {
                int m = wm + mt * 16 + r;
                a[mt][0] = Au[m * ALD + ks * 8 + c];
                a[mt][1] = Au[(m + 8) * ALD + ks * 8 + c];
                a[mt][2] = Au[m * ALD + ks * 8 + c + 4];
                a[mt][3] = Au[(m + 8) * ALD + ks * 8 + c + 4];
            }
#pragma unroll
            for (int nt = 0; nt < 8; nt++) {
                b[nt][0] = Bu[(ks * 8 + c) * BLD + wn + nt * 8 + r];
                b[nt][1] = Bu[(ks * 8 + c + 4) * BLD + wn + nt * 8 + r];
            }
#pragma unroll
            for (int mt = 0; mt < 2; mt++)
#pragma unroll
                for (int nt = 0; nt < 8; nt++) mma_tf32(acc[mt][nt], a[mt], b[nt]);
        }
        __syncthreads();
    }

#pragma unroll
    for (int mt = 0; mt < 2; mt++)
#pragma unroll
        for (int nt = 0; nt < 8; nt++) {
            int gm0 = m0 + wm + mt * 16 + r;
            int gn = n0 + wn + nt * 8 + 2 * c;
#pragma unroll
            for (int h = 0; h < 2; h++) {
                int gm = gm0 + h * 8;
                float2 val;
                val.x = acc[mt][nt][h * 2];
                val.y = acc[mt][nt][h * 2 + 1];
                if (EPI == 2 || EPI == 3) { val.x += bias[gn]; val.y += bias[gn + 1]; }
                if (EPI == 2) { val.x = gelu_f(val.x); val.y = gelu_f(val.y); }
                if (EPI == 3) {
                    const float2 ad = *(const float2*)(addend + (size_t)gm * ldc + gn);
                    val.x += ad.x; val.y += ad.y;
                }
                if (ROUND) { val.x = rnd_tf32(val.x); val.y = rnd_tf32(val.y); }
                *(float2*)(C + (size_t)gm * ldc + gn) = val;
            }
        }
}

// ---------------- pipelined scores: logits = q k^T / 16 + bias + causal ----------------
__global__ __launch_bounds__(256)
void scores_pipe(const float* __restrict__ q, const float* __restrict__ k,
                 const float* __restrict__ ab, float* __restrict__ sc) {
    int h = blockIdx.z;
    int m0 = blockIdx.y * BM, n0 = blockIdx.x * BN;
    float* out = sc + ((size_t)h << 22);
    int tid = threadIdx.x;

    if (n0 > m0 + BM - 1) {  // fully masked block
        for (int e = tid; e < BM * BN; e += 256) {
            int m = e >> 7, n = e & 127;
            size_t idx = (size_t)(m0 + m) * SEQ + (n0 + n);
            out[idx] = ab[idx] - 1e10f;
        }
        return;
    }

    extern __shared__ float sm[];
    float* Asm = sm;
    float* Bsm = sm + STAGES * A_STAGE_W;   // B tile n-major [128][ALD]

    const float* Ag = q + (size_t)h * DH + (size_t)(m0 + (tid >> 3)) * DM + (tid & 7) * 4;
    const float* Bg = k + (size_t)h * DH + (size_t)(n0 + (tid >> 3)) * DM + (tid & 7) * 4;
    unsigned sA0 = smem_u32(Asm) + ((tid >> 3) * ALD + (tid & 7) * 4) * 4;
    unsigned sB0 = smem_u32(Bsm) + ((tid >> 3) * ALD + (tid & 7) * 4) * 4;

    auto issue = [&](int t) {
        int st = t % STAGES;
        int k0 = t * BK;
        unsigned a = sA0 + st * (A_STAGE_W * 4);
        unsigned b = sB0 + st * (S_STAGE_W * 4);
#pragma unroll
        for (int i = 0; i < 4; i++) {
            CP_A16(a + i * 32 * ALD * 4, Ag + (size_t)i * 32 * DM + k0);
            CP_A16(b + i * 32 * ALD * 4, Bg + (size_t)i * 32 * DM + k0);
        }
    };

    const int nk = DH / BK;  // 8
    issue(0); CP_COMMIT();
    issue(1); CP_COMMIT();

    int warp = tid >> 5, lane = tid & 31;
    int wm = (warp & 3) * 32, wn = (warp >> 2) * 64;
    int r = lane >> 2, c = lane & 3;

    float acc[2][8][4];
#pragma unroll
    for (int i = 0; i < 2; i++)
#pragma unroll
        for (int j = 0; j < 8; j++)
#pragma unroll
            for (int qq = 0; qq < 4; qq++) acc[i][j][qq] = 0.f;

    for (int t = 0; t < nk; t++) {
        CP_WAIT1();
        __syncthreads();
        if (t + 2 < nk) issue(t + 2);
        CP_COMMIT();

        const unsigned* Au = reinterpret_cast<const unsigned*>(Asm + (t % STAGES) * A_STAGE_W);
        const unsigned* Bu = reinterpret_cast<const unsigned*>(Bsm + (t % STAGES) * S_STAGE_W);
#pragma unroll
        for (int ks = 0; ks < BK / 8; ks++) {
            unsigned a[2][4], b[8][2];
#pragma unroll
            for (int mt = 0; mt < 2; mt++) {
                int m = wm + mt * 16 + r;
                a[mt][0] = Au[m * ALD + ks * 8 + c];
                a[mt][1] = Au[(m + 8) * ALD + ks * 8 + c];
                a[mt][2] = Au[m * ALD + ks * 8 + c + 4];
                a[mt][3] = Au[(m + 8) * ALD + ks * 8 + c + 4];
            }
#pragma unroll
            for (int nt = 0; nt < 8; nt++) {
                int n = wn + nt * 8 + r;
                b[nt][0] = Bu[n * ALD + ks * 8 + c];
                b[nt][1] = Bu[n * ALD + ks * 8 + c + 4];
            }
#pragma unroll
            for (int mt = 0; mt < 2; mt++)
#pragma unroll
                for (int nt = 0; nt < 8; nt++) mma_tf32(acc[mt][nt], a[mt], b[nt]);
        }
        __syncthreads();
    }

    const float scale = 1.0f / 16.0f;
#pragma unroll
    for (int mt = 0; mt < 2; mt++)
#pragma unroll
        for (int nt = 0; nt < 8; nt++) {
            int gm0 = m0 + wm + mt * 16 + r;
            int gn = n0 + wn + nt * 8 + 2 * c;
#pragma unroll
            for (int hh = 0; hh < 2; hh++) {
                int gm = gm0 + hh * 8;
                size_t base = (size_t)gm * SEQ + gn;
                out[base]     = acc[mt][nt][hh * 2]     * scale + ab[base]     + ((gn     > gm) ? -1e10f : 0.f);
                out[base + 1] = acc[mt][nt][hh * 2 + 1] * scale + ab[base + 1] + ((gn + 1 > gm) ? -1e10f : 0.f);
            }
        }
}

// ---------------- softmax over last dim (stores tf32-rounded weights) ----------------
__global__ void softmax_kernel(float* __restrict__ sc) {
    size_t row = blockIdx.x;
    float* p = sc + row * SEQ;
    __shared__ float red[256];
    int tid = threadIdx.x;

    float vals[8];
    float m = -3.4e38f;
#pragma unroll
    for (int i = 0; i < 8; i++) { vals[i] = p[tid + i * 256]; m = fmaxf(m, vals[i]); }
    red[tid] = m; __syncthreads();
    for (int s = 128; s > 0; s >>= 1) { if (tid < s) red[tid] = fmaxf(red[tid], red[tid + s]); __syncthreads(); }
    m = red[0]; __syncthreads();

    float sum = 0.f;
#pragma unroll
    for (int i = 0; i < 8; i++) { vals[i] = expf(vals[i] - m); sum += vals[i]; }
    red[tid] = sum; __syncthreads();
    for (int s = 128; s > 0; s >>= 1) { if (tid < s) red[tid] += red[tid + s]; __syncthreads(); }
    float inv = 1.0f / red[0];
#pragma unroll
    for (int i = 0; i < 8; i++) p[tid + i * 256] = rnd_tf32(vals[i] * inv);
}

// ---------------- launch ----------------
extern "C" void kernel_launch(void* const* d_in, const int* in_sizes, int n_in,
                              void* d_out, int out_size) {
    const float* x   = (const float*)d_in[0];
    const float* ab  = (const float*)d_in[1];
    const float* lns = (const float*)d_in[2];
    const float* lno = (const float*)d_in[3];
    const float* wq  = (const float*)d_in[4];
    const float* wk  = (const float*)d_in[5];
    const float* wv  = (const float*)d_in[6];
    const float* wo  = (const float*)d_in[7];
    const float* w1  = (const float*)d_in[8];
    const float* b1  = (const float*)d_in[9];
    const float* w2  = (const float*)d_in[10];
    const float* b2  = (const float*)d_in[11];
    float* out = (float*)d_out;

    float *xn, *q, *k, *v, *av, *ao, *f1, *scr;
    float *rwq, *rwk, *rwv, *rwo, *rw1, *rw2;
    cudaGetSymbolAddress((void**)&xn,  g_xn);
    cudaGetSymbolAddress((void**)&q,   g_q);
    cudaGetSymbolAddress((void**)&k,   g_k);
    cudaGetSymbolAddress((void**)&v,   g_v);
    cudaGetSymbolAddress((void**)&av,  g_av);
    cudaGetSymbolAddress((void**)&ao,  g_ao);
    cudaGetSymbolAddress((void**)&f1,  g_f1);
    cudaGetSymbolAddress((void**)&scr, g_sc);
    cudaGetSymbolAddress((void**)&rwq, g_rwq);
    cudaGetSymbolAddress((void**)&rwk, g_rwk);
    cudaGetSymbolAddress((void**)&rwv, g_rwv);
    cudaGetSymbolAddress((void**)&rwo, g_rwo);
    cudaGetSymbolAddress((void**)&rw1, g_rw1);
    cudaGetSymbolAddress((void**)&rw2, g_rw2);

    const int GEMM_SMEM = STAGES * (A_STAGE_W + B_STAGE_W) * 4;   // 107,520 B
    const int SC_SMEM   = STAGES * (A_STAGE_W + S_STAGE_W) * 4;   // 110,592 B
    cudaFuncSetAttribute(gemm_pipe<0,1>, cudaFuncAttributeMaxDynamicSharedMemorySize, GEMM_SMEM);
    cudaFuncSetAttribute(gemm_pipe<0,0>, cudaFuncAttributeMaxDynamicSharedMemorySize, GEMM_SMEM);
    cudaFuncSetAttribute(gemm_pipe<2,1>, cudaFuncAttributeMaxDynamicSharedMemorySize, GEMM_SMEM);
    cudaFuncSetAttribute(gemm_pipe<3,0>, cudaFuncAttributeMaxDynamicSharedMemorySize, GEMM_SMEM);
    cudaFuncSetAttribute(scores_pipe,    cudaFuncAttributeMaxDynamicSharedMemorySize, SC_SMEM);

    // 0. round weights to tf32 bit patterns
    round_kernel<<<2048, 256>>>((const float4*)wq, (float4*)rwq, (size_t)DM * DM / 4);
    round_kernel<<<2048, 256>>>((const float4*)wk, (float4*)rwk, (size_t)DM * DM / 4);
    round_kernel<<<2048, 256>>>((const float4*)wv, (float4*)rwv, (size_t)DM * DM / 4);
    round_kernel<<<2048, 256>>>((const float4*)wo, (float4*)rwo, (size_t)DM * DM / 4);
    round_kernel<<<4096, 256>>>((const float4*)w1, (float4*)rw1, (size_t)DM * DFF / 4);
    round_kernel<<<4096, 256>>>((const float4*)w2, (float4*)rw2, (size_t)DFF * DM / 4);

    // 1. LayerNorm (rounded output)
    ln_kernel<<<SEQ, 256>>>(x, lns, lno, xn);

    // 2. QKV projections (rounded outputs; q,k re-rounded post-RoPE)
    dim3 g1(DM / BN, SEQ / BM);
    gemm_pipe<0,1><<<g1, 256, GEMM_SMEM>>>(xn, rwq, q, DM, DM, DM, DM, 0, 0, 0, nullptr, nullptr, 0);
    gemm_pipe<0,1><<<g1, 256, GEMM_SMEM>>>(xn, rwk, k, DM, DM, DM, DM, 0, 0, 0, nullptr, nullptr, 0);
    gemm_pipe<0,1><<<g1, 256, GEMM_SMEM>>>(xn, rwv, v, DM, DM, DM, DM, 0, 0, 0, nullptr, nullptr, 0);

    // 3. RoPE (+rounding)
    rope_kernel<<<SEQ, 512>>>(q, k);

    // 4. logits + mask + bias
    dim3 gs(SEQ / BN, SEQ / BM, NH);
    scores_pipe<<<gs, 256, SC_SMEM>>>(q, k, ab, scr);

    // 5. softmax (rounded output)
    softmax_kernel<<<NH * SEQ, 256>>>(scr);

    // 6. attn_vec = weights @ v (causal K-bound, rounded output)
    dim3 gav(DH / BN, SEQ / BM, NH);
    gemm_pipe<0,1><<<gav, 256, GEMM_SMEM>>>(scr, v, av, SEQ, SEQ, DM, DM,
                                            (long)SEQ * SEQ, (long)DH, (long)DH, nullptr, nullptr, 1);

    // 7. attn_out = attn_vec @ wo (no rounding; addend only)
    gemm_pipe<0,0><<<g1, 256, GEMM_SMEM>>>(av, rwo, ao, DM, DM, DM, DM, 0, 0, 0, nullptr, nullptr, 0);

    // 8. ffn hidden = gelu(xn @ w1 + b1) (rounded)
    dim3 gf1(DFF / BN, SEQ / BM);
    gemm_pipe<2,1><<<gf1, 256, GEMM_SMEM>>>(xn, rw1, f1, DM, DM, DFF, DFF, 0, 0, 0, b1, nullptr, 0);

    // 9. out = f1 @ w2 + b2 + attn_out
    gemm_pipe<3,0><<<g1, 256, GEMM_SMEM>>>(f1, rw2, out, DFF, DFF, DM, DM, 0, 0, 0, b2, ao, 0);
}

// round 4
// speedup vs baseline: 1.9284x; 1.7190x over previous
#include <cuda_runtime.h>
#include <cuda_fp16.h>
#include <math.h>
#include <stdint.h>

#define SEQ  2048
#define DM   4096
#define NH   16
#define DH   256
#define DFF  16384
#define LDQKV (3 * DM)

#define BM 128
#define BN 256
#define BK 32          // halves per k-step
#define STG 4
#define ROWH 40        // padded row length in halves (80B)
#define A_H (BM * ROWH)        // 5120 halves
#define B_H (BN * ROWH)        // 10240 halves
#define SLOT_H (A_H + B_H)     // 15360 halves
#define SLOT_B (SLOT_H * 2)    // 30720 bytes
#define SMEM_B (STG * SLOT_B)  // 122880 bytes

// ---------------- device scratch ----------------
__device__ __half g_xn [(size_t)SEQ * DM];
__device__ __half g_qkv[(size_t)SEQ * LDQKV];
__device__ __half g_vt [(size_t)DM * SEQ];          // v^T: [h*256+d][T]
__device__ __half g_av [(size_t)SEQ * DM];
__device__ float  g_ao [(size_t)SEQ * DM];
__device__ __half g_f1 [(size_t)SEQ * DFF];
__device__ float  g_sc [(size_t)NH * SEQ * SEQ];    // logits
__device__ __half g_wt [(size_t)NH * SEQ * SEQ];    // softmax weights
// fp16 transposed weights [N][K]
__device__ __half g_wqkv[(size_t)LDQKV * DM];
__device__ __half g_wo  [(size_t)DM * DM];
__device__ __half g_w1t [(size_t)DFF * DM];
__device__ __half g_w2t [(size_t)DM * DFF];

// ---------------- helpers ----------------
__device__ __forceinline__ float gelu_f(float x) {
    float t = tanhf(0.7978845608028654f * (x + 0.044715f * x * x * x));
    return 0.5f * x * (1.0f + t);
}
__device__ __forceinline__ unsigned smem_u32(const void* p) {
    return (unsigned)__cvta_generic_to_shared(p);
}

#define CP_A16(saddr, gptr) \
    asm volatile("cp.async.cg.shared.global [%0], [%1], 16;\n" :: "r"(saddr), "l"(gptr))
#define CP_COMMIT() asm volatile("cp.async.commit_group;\n" ::: "memory")
#define CP_WAIT2()  asm volatile("cp.async.wait_group 2;\n" ::: "memory")
#define CP_WAIT0()  asm volatile("cp.async.wait_group 0;\n" ::: "memory")

#define LDSM4(r, addr) \
    asm volatile("ldmatrix.sync.aligned.m8n8.x4.shared.b16 {%0,%1,%2,%3}, [%4];" \
        : "=r"((r)[0]), "=r"((r)[1]), "=r"((r)[2]), "=r"((r)[3]) : "r"(addr))

__device__ __forceinline__ void mma16(float c[4], const uint32_t a[4], uint32_t b0, uint32_t b1) {
    asm volatile(
        "mma.sync.aligned.m16n8k16.row.col.f32.f16.f16.f32 "
        "{%0,%1,%2,%3},{%4,%5,%6,%7},{%8,%9},{%0,%1,%2,%3};"
        : "+f"(c[0]), "+f"(c[1]), "+f"(c[2]), "+f"(c[3])
        : "r"(a[0]), "r"(a[1]), "r"(a[2]), "r"(a[3]), "r"(b0), "r"(b1));
}

template <typename T> __device__ __forceinline__ void store2(T* p, float x, float y);
template <> __device__ __forceinline__ void store2<float>(float* p, float x, float y) {
    *(float2*)p = make_float2(x, y);
}
template <> __device__ __forceinline__ void store2<__half>(__half* p, float x, float y) {
    *(__half2*)p = __floats2half2_rn(x, y);
}

// ================= generic FP16 GEMM: C[M][N] = A[M][K] @ BT[N][K]^T =================
// block 128x256, 8 warps (2x4), warp 64x64, BK=32, 4-stage cp.async + ldmatrix
// EPI: 0 = store acc; 2 = store gelu(acc+bias); 3 = store acc+bias+addend
template <int EPI, typename OutT>
__global__ __launch_bounds__(256)
void gemm16(const __half* __restrict__ A, const __half* __restrict__ BT,
            OutT* __restrict__ C, int K, int lda, int ldb, int ldc,
            long sAz, long sBz, long sCz,
            const float* __restrict__ bias, const float* __restrict__ addend,
            int causal) {
    extern __shared__ __half smh[];
    A  += (size_t)blockIdx.z * sAz;
    BT += (size_t)blockIdx.z * sBz;
    C  += (size_t)blockIdx.z * sCz;
    int m0 = blockIdx.y * BM, n0 = blockIdx.x * BN;
    int tid = threadIdx.x, warp = tid >> 5, lane = tid & 31;

    int kend = causal ? ((m0 + BM < K) ? (m0 + BM) : K) : K;
    int nk = kend / BK;

    uint32_t sb = smem_u32(smh);
    const __half* Ag = A + (size_t)(m0 + (tid >> 2)) * lda + (tid & 3) * 8;
    const __half* Bg = BT + (size_t)(n0 + (tid >> 2)) * ldb + (tid & 3) * 8;
    uint32_t Ad = sb + ((tid >> 2) * ROWH + (tid & 3) * 8) * 2;
    uint32_t Bd = sb + (A_H + (tid >> 2) * ROWH + (tid & 3) * 8) * 2;

    auto issue = [&](int t) {
        uint32_t off = (t & 3) * SLOT_B;
        int k0 = t * BK;
#pragma unroll
        for (int i = 0; i < 2; i++)
            CP_A16(Ad + off + i * 64 * ROWH * 2, Ag + (size_t)i * 64 * lda + k0);
#pragma unroll
        for (int i = 0; i < 4; i++)
            CP_A16(Bd + off + i * 64 * ROWH * 2, Bg + (size_t)i * 64 * ldb + k0);
    };

    issue(0); CP_COMMIT();
    if (nk > 1) issue(1);
    CP_COMMIT();
    if (nk > 2) issue(2);
    CP_COMMIT();

    int wm = (warp >> 2) * 64, wn = (warp & 3) * 64;
    uint32_t aAddr = sb + ((wm + (lane & 15)) * ROWH + (lane >> 4) * 8) * 2;
    uint32_t bAddr = sb + A_H * 2 +
                     ((wn + (lane & 7) + ((lane >> 4) & 1) * 8) * ROWH + ((lane >> 3) & 1) * 8) * 2;

    float acc[4][8][4];
#pragma unroll
    for (int i = 0; i < 4; i++)
#pragma unroll
        for (int j = 0; j < 8; j++)
#pragma unroll
            for (int q = 0; q < 4; q++) acc[i][j][q] = 0.f;

    for (int t = 0; t < nk; t++) {
        CP_WAIT2();
        __syncthreads();
        int u = t + 3;
        if (u < nk) issue(u);
        CP_COMMIT();

        uint32_t so = (t & 3) * SLOT_B;
#pragma unroll
        for (int ks = 0; ks < 2; ks++) {
            uint32_t a[4][4], b[4][4];
#pragma unroll
            for (int mt = 0; mt < 4; mt++)
                LDSM4(a[mt], aAddr + so + mt * (16 * ROWH * 2) + ks * 32);
#pragma unroll
            for (int p = 0; p < 4; p++)
                LDSM4(b[p], bAddr + so + p * (16 * ROWH * 2) + ks * 32);
#pragma unroll
            for (int mt = 0; mt < 4; mt++)
#pragma unroll
                for (int nt = 0; nt < 8; nt++)
                    mma16(acc[mt][nt], a[mt], b[nt >> 1][(nt & 1) * 2], b[nt >> 1][(nt & 1) * 2 + 1]);
        }
    }

    CP_WAIT0();
    __syncthreads();

    int r = lane >> 2, c2 = 2 * (lane & 3);
#pragma unroll
    for (int mt = 0; mt < 4; mt++)
#pragma unroll
        for (int nt = 0; nt < 8; nt++) {
            int gm0 = m0 + wm + mt * 16 + r;
            int gn = n0 + wn + nt * 8 + c2;
#pragma unroll
            for (int h = 0; h < 2; h++) {
                int gm = gm0 + h * 8;
                float vx = acc[mt][nt][h * 2], vy = acc[mt][nt][h * 2 + 1];
                if (EPI == 2 || EPI == 3) {
                    const float2 bb = *(const float2*)(bias + gn);
                    vx += bb.x; vy += bb.y;
                }
                if (EPI == 2) { vx = gelu_f(vx); vy = gelu_f(vy); }
                if (EPI == 3) {
                    const float2 ad = *(const float2*)(addend + (size_t)gm * ldc + gn);
                    vx += ad.x; vy += ad.y;
                }
                store2<OutT>(C + (size_t)gm * ldc + gn, vx, vy);
            }
        }
}

// ================= scores: logits = q k^T / 16 + ab (+causal mask), fp32 out =================
__global__ __launch_bounds__(256)
void scores16(const __half* __restrict__ qkv, const float* __restrict__ ab,
              float* __restrict__ sc) {
    int h = blockIdx.z;
    int m0 = blockIdx.y * BM, n0 = blockIdx.x * BN;
    if (n0 > m0 + BM - 1) return;   // fully masked: softmax never reads here
    float* out = sc + ((size_t)h << 22);

    extern __shared__ __half smh[];
    int tid = threadIdx.x, warp = tid >> 5, lane = tid & 31;
    uint32_t sb = smem_u32(smh);

    const __half* Ag = qkv + (size_t)h * DH + (size_t)(m0 + (tid >> 2)) * LDQKV + (tid & 3) * 8;
    const __half* Bg = qkv + DM + (size_t)h * DH + (size_t)(n0 + (tid >> 2)) * LDQKV + (tid & 3) * 8;
    uint32_t Ad = sb + ((tid >> 2) * ROWH + (tid & 3) * 8) * 2;
    uint32_t Bd = sb + (A_H + (tid >> 2) * ROWH + (tid & 3) * 8) * 2;

    auto issue = [&](int t) {
        uint32_t off = (t & 3) * SLOT_B;
        int k0 = t * BK;
#pragma unroll
        for (int i = 0; i < 2; i++)
            CP_A16(Ad + off + i * 64 * ROWH * 2, Ag + (size_t)i * 64 * LDQKV + k0);
#pragma unroll
        for (int i = 0; i < 4; i++)
            CP_A16(Bd + off + i * 64 * ROWH * 2, Bg + (size_t)i * 64 * LDQKV + k0);
    };

    const int nk = DH / BK;   // 8
    issue(0); CP_COMMIT();
    issue(1); CP_COMMIT();
    issue(2); CP_COMMIT();

    int wm = (warp >> 2) * 64, wn = (warp & 3) * 64;
    uint32_t aAddr = sb + ((wm + (lane & 15)) * ROWH + (lane >> 4) * 8) * 2;
    uint32_t bAddr = sb + A_H * 2 +
                     ((wn + (lane & 7) + ((lane >> 4) & 1) * 8) * ROWH + ((lane >> 3) & 1) * 8) * 2;

    float acc[4][8][4];
#pragma unroll
    for (int i = 0; i < 4; i++)
#pragma unroll
        for (int j = 0; j < 8; j++)
#pragma unroll
            for (int q = 0; q < 4; q++) acc[i][j][q] = 0.f;

    for (int t = 0; t < nk; t++) {
        CP_WAIT2();
        __syncthreads();
        int u = t + 3;
        if (u < nk) issue(u);
        CP_COMMIT();
        uint32_t so = (t & 3) * SLOT_B;
#pragma unroll
        for (int ks = 0; ks < 2; ks++) {
            uint32_t a[4][4], b[4][4];
#pragma unroll
            for (int mt = 0; mt < 4; mt++)
                LDSM4(a[mt], aAddr + so + mt * (16 * ROWH * 2) + ks * 32);
#pragma unroll
            for (int p = 0; p < 4; p++)
                LDSM4(b[p], bAddr + so + p * (16 * ROWH * 2) + ks * 32);
#pragma unroll
            for (int mt = 0; mt < 4; mt++)
#pragma unroll
                for (int nt = 0; nt < 8; nt++)
                    mma16(acc[mt][nt], a[mt], b[nt >> 1][(nt & 1) * 2], b[nt >> 1][(nt & 1) * 2 + 1]);
        }
    }

    CP_WAIT0();
    __syncthreads();

    const float scale = 1.0f / 16.0f;
    int r = lane >> 2, c2 = 2 * (lane & 3);
#pragma unroll
    for (int mt = 0; mt < 4; mt++)
#pragma unroll
        for (int nt = 0; nt < 8; nt++) {
            int gm0 = m0 + wm + mt * 16 + r;
            int gn = n0 + wn + nt * 8 + c2;
#pragma unroll
            for (int hh = 0; hh < 2; hh++) {
                int gm = gm0 + hh * 8;
                size_t base = (size_t)gm * SEQ + gn;
                const float2 bb = *(const float2*)(ab + base);
                float vx = acc[mt][nt][hh * 2] * scale + bb.x + ((gn > gm) ? -1e10f : 0.f);
                float vy = acc[mt][nt][hh * 2 + 1] * scale + bb.y + ((gn + 1 > gm) ? -1e10f : 0.f);
                *(float2*)(out + base) = make_float2(vx, vy);
            }
        }
}

// ================= softmax over causal prefix; writes fp16 weights, zero-pads to 128-bdy =================
__global__ void softmax16(const float* __restrict__ sc, __half* __restrict__ wt) {
    int b = blockIdx.x;
    int h = b >> 11, t = b & 2047;
    const float* p = sc + ((size_t)h << 22) + (size_t)t * SEQ;
    __half* w = wt + ((size_t)h << 22) + (size_t)t * SEQ;
    int n = t + 1;
    int len = ((t >> 7) + 1) << 7;
    __shared__ float red[256];
    int tid = threadIdx.x;

    float vals[8];
    float m = -3.4e38f;
#pragma unroll
    for (int i = 0; i < 8; i++) {
        int j = tid + i * 256;
        vals[i] = (j < n) ? p[j] : -3.4e38f;
        m = fmaxf(m, vals[i]);
    }
    red[tid] = m; __syncthreads();
    for (int s = 128; s > 0; s >>= 1) { if (tid < s) red[tid] = fmaxf(red[tid], red[tid + s]); __syncthreads(); }
    m = red[0]; __syncthreads();

    float sum = 0.f;
#pragma unroll
    for (int i = 0; i < 8; i++) {
        int j = tid + i * 256;
        if (j < n) { vals[i] = expf(vals[i] - m); sum += vals[i]; }
    }
    red[tid] = sum; __syncthreads();
    for (int s = 128; s > 0; s >>= 1) { if (tid < s) red[tid] += red[tid + s]; __syncthreads(); }
    float inv = 1.0f / red[0];
#pragma unroll
    for (int i = 0; i < 8; i++) {
        int j = tid + i * 256;
        if (j < n)        w[j] = __float2half(vals[i] * inv);
        else if (j < len) w[j] = __float2half(0.f);
    }
}

// ================= weight transpose + fp32->fp16: dst[n][k] = src[k][n] =================
__global__ void trw(const float* __restrict__ src, __half* __restrict__ dst, int K, int N) {
    __shared__ float tile[32][33];
    int k0 = blockIdx.y * 32, n0 = blockIdx.x * 32;
    int tx = threadIdx.x, ty = threadIdx.y;
#pragma unroll
    for (int i = 0; i < 4; i++)
        tile[ty + i * 8][tx] = src[(size_t)(k0 + ty + i * 8) * N + n0 + tx];
    __syncthreads();
#pragma unroll
    for (int i = 0; i < 4; i++)
        dst[(size_t)(n0 + ty + i * 8) * K + k0 + tx] = __float2half(tile[tx][ty + i * 8]);
}

// ================= v transpose (half): vt[c][T] = qkv[T][2*DM + c] =================
__global__ void trv(const __half* __restrict__ qkv, __half* __restrict__ vt) {
    __shared__ __half tile[32][33];
    int c0 = blockIdx.x * 32, T0 = blockIdx.y * 32;
    int tx = threadIdx.x, ty = threadIdx.y;
#pragma unroll
    for (int i = 0; i < 4; i++)
        tile[ty + i * 8][tx] = qkv[(size_t)(T0 + ty + i * 8) * LDQKV + 2 * DM + c0 + tx];
    __syncthreads();
#pragma unroll
    for (int i = 0; i < 4; i++)
        vt[(size_t)(c0 + ty + i * 8) * SEQ + T0 + tx] = tile[tx][ty + i * 8];
}

// ================= layernorm -> half =================
__global__ void ln_kernel(const float* __restrict__ x, const float* __restrict__ sc,
                          const float* __restrict__ of, __half* __restrict__ xn) {
    int row = blockIdx.x;
    const float* xr = x + (size_t)row * DM;
    __half* xo = xn + (size_t)row * DM;
    __shared__ float red[256];
    int tid = threadIdx.x;
    float s = 0.f;
    for (int j = tid; j < DM; j += 256) s += xr[j];
    red[tid] = s; __syncthreads();
    for (int st = 128; st > 0; st >>= 1) { if (tid < st) red[tid] += red[tid + st]; __syncthreads(); }
    float mean = red[0] * (1.0f / DM);
    __syncthreads();
    float v = 0.f;
    for (int j = tid; j < DM; j += 256) { float d = xr[j] - mean; v += d * d; }
    red[tid] = v; __syncthreads();
    for (int st = 128; st > 0; st >>= 1) { if (tid < st) red[tid] += red[tid + st]; __syncthreads(); }
    float rstd = rsqrtf(red[0] * (1.0f / DM) + 1e-5f);
    for (int j = tid; j < DM; j += 256)
        xo[j] = __float2half(sc[j] * rstd * (xr[j] - mean) + of[j]);
}

// ================= RoPE on half q,k =================
__global__ void rope_kernel(__half* __restrict__ qkv) {
    int t = blockIdx.x, tid = threadIdx.x;
    __shared__ float ss[32], cc[32];
    if (tid < 32) {
        double inv = pow(10000.0, -((double)(2 * tid)) / 64.0);
        double a = (double)t * inv;
        ss[tid] = (float)sin(a); cc[tid] = (float)cos(a);
    }
    __syncthreads();
    int head = tid >> 5, i = tid & 31;
    float s = ss[i], co = cc[i];
    size_t qoff = (size_t)t * LDQKV + head * DH + 2 * i;
    size_t koff = qoff + DM;
    float q0 = __half2float(qkv[qoff]), q1 = __half2float(qkv[qoff + 1]);
    qkv[qoff]     = __float2half(q0 * co - q1 * s);
    qkv[qoff + 1] = __float2half(q1 * co + q0 * s);
    float k0 = __half2float(qkv[koff]), k1 = __half2float(qkv[koff + 1]);
    qkv[koff]     = __float2half(k0 * co - k1 * s);
    qkv[koff + 1] = __float2half(k1 * co + k0 * s);
}

// ================= launch =================
extern "C" void kernel_launch(void* const* d_in, const int* in_sizes, int n_in,
                              void* d_out, int out_size) {
    const float* x   = (const float*)d_in[0];
    const float* ab  = (const float*)d_in[1];
    const float* lns = (const float*)d_in[2];
    const float* lno = (const float*)d_in[3];
    const float* wq  = (const float*)d_in[4];
    const float* wk  = (const float*)d_in[5];
    const float* wv  = (const float*)d_in[6];
    const float* wo  = (const float*)d_in[7];
    const float* w1  = (const float*)d_in[8];
    const float* b1  = (const float*)d_in[9];
    const float* w2  = (const float*)d_in[10];
    const float* b2  = (const float*)d_in[11];
    float* out = (float*)d_out;

    __half *xn, *qkv, *vt, *av, *f1, *wt, *wqkv16, *wo16, *w1t16, *w2t16;
    float *ao, *scr;
    cudaGetSymbolAddress((void**)&xn,     g_xn);
    cudaGetSymbolAddress((void**)&qkv,    g_qkv);
    cudaGetSymbolAddress((void**)&vt,     g_vt);
    cudaGetSymbolAddress((void**)&av,     g_av);
    cudaGetSymbolAddress((void**)&ao,     g_ao);
    cudaGetSymbolAddress((void**)&f1,     g_f1);
    cudaGetSymbolAddress((void**)&scr,    g_sc);
    cudaGetSymbolAddress((void**)&wt,     g_wt);
    cudaGetSymbolAddress((void**)&wqkv16, g_wqkv);
    cudaGetSymbolAddress((void**)&wo16,   g_wo);
    cudaGetSymbolAddress((void**)&w1t16,  g_w1t);
    cudaGetSymbolAddress((void**)&w2t16,  g_w2t);

    cudaFuncSetAttribute(gemm16<0, __half>, cudaFuncAttributeMaxDynamicSharedMemorySize, SMEM_B);
    cudaFuncSetAttribute(gemm16<0, float>,  cudaFuncAttributeMaxDynamicSharedMemorySize, SMEM_B);
    cudaFuncSetAttribute(gemm16<2, __half>, cudaFuncAttributeMaxDynamicSharedMemorySize, SMEM_B);
    cudaFuncSetAttribute(gemm16<3, float>,  cudaFuncAttributeMaxDynamicSharedMemorySize, SMEM_B);
    cudaFuncSetAttribute(scores16,          cudaFuncAttributeMaxDynamicSharedMemorySize, SMEM_B);

    dim3 tb(32, 8);
    // 0. weights: transpose + convert to fp16 [N][K]
    trw<<<dim3(DM / 32, DM / 32), tb>>>(wq, wqkv16, DM, DM);
    trw<<<dim3(DM / 32, DM / 32), tb>>>(wk, wqkv16 + (size_t)DM * DM, DM, DM);
    trw<<<dim3(DM / 32, DM / 32), tb>>>(wv, wqkv16 + (size_t)2 * DM * DM, DM, DM);
    trw<<<dim3(DM / 32, DM / 32), tb>>>(wo, wo16, DM, DM);
    trw<<<dim3(DFF / 32, DM / 32), tb>>>(w1, w1t16, DM, DFF);
    trw<<<dim3(DM / 32, DFF / 32), tb>>>(w2, w2t16, DFF, DM);

    // 1. LayerNorm -> half
    ln_kernel<<<SEQ, 256>>>(x, lns, lno, xn);

    // 2. fused QKV: [2048 x 12288]
    gemm16<0, __half><<<dim3(LDQKV / BN, SEQ / BM), 256, SMEM_B>>>(
        xn, wqkv16, qkv, DM, DM, DM, LDQKV, 0, 0, 0, nullptr, nullptr, 0);

    // 3. RoPE
    rope_kernel<<<SEQ, 512>>>(qkv);

    // 4. v^T for AV B-operand
    trv<<<dim3(DM / 32, SEQ / 32), tb>>>(qkv, vt);

    // 5. scores (masked blocks skipped)
    scores16<<<dim3(SEQ / BN, SEQ / BM, NH), 256, SMEM_B>>>(qkv, ab, scr);

    // 6. softmax -> fp16 weights (+ zero pad to 128-boundary)
    softmax16<<<NH * SEQ, 256>>>(scr, wt);

    // 7. attn_vec = weights @ v  (causal K-bound), half out
    gemm16<0, __half><<<dim3(1, SEQ / BM, NH), 256, SMEM_B>>>(
        wt, vt, av, SEQ, SEQ, SEQ, DM,
        (long)SEQ * SEQ, (long)DH * SEQ, (long)DH, nullptr, nullptr, 1);

    // 8. attn_out = av @ wo, fp32
    gemm16<0, float><<<dim3(DM / BN, SEQ / BM), 256, SMEM_B>>>(
        av, wo16, ao, DM, DM, DM, DM, 0, 0, 0, nullptr, nullptr, 0);

    // 9. f1 = gelu(xn @ w1 + b1), half
    gemm16<2, __half><<<dim3(DFF / BN, SEQ / BM), 256, SMEM_B>>>(
        xn, w1t16, f1, DM, DM, DM, DFF, 0, 0, 0, b1, nullptr, 0);

    // 10. out = f1 @ w2 + b2 + ao, fp32
    gemm16<3, float><<<dim3(DM / BN, SEQ / BM), 256, SMEM_B>>>(
        f1, w2t16, out, DFF, DFF, DFF, DM, 0, 0, 0, b2, ao, 0);
}

// round 5
// speedup vs baseline: 2.3873x; 1.2380x over previous
#include <cuda_runtime.h>
#include <cuda_fp16.h>
#include <math.h>
#include <stdint.h>

#define SEQ  2048
#define DM   4096
#define NH   16
#define DH   256
#define DFF  16384
#define LDQKV (3 * DM)

#define BM 128
#define BN 128
#define BK 32          // halves per k-step
#define STG 4
#define ROWH 40        // padded row length in halves (80B)
#define A_H (BM * ROWH)        // 5120 halves
#define B_H (BN * ROWH)        // 5120 halves
#define SLOT_H (A_H + B_H)     // 10240 halves
#define SLOT_B (SLOT_H * 2)    // 20480 bytes
#define SMEM_B (STG * SLOT_B)  // 81920 bytes -> 2 CTAs/SM

// ---------------- device scratch ----------------
__device__ __half g_xn [(size_t)SEQ * DM];
__device__ __half g_qkv[(size_t)SEQ * LDQKV];
__device__ __half g_vt [(size_t)DM * SEQ];          // v^T: [h*256+d][T]
__device__ __half g_av [(size_t)SEQ * DM];
__device__ float  g_ao [(size_t)SEQ * DM];
__device__ __half g_f1 [(size_t)SEQ * DFF];
__device__ float  g_sc [(size_t)NH * SEQ * SEQ];    // logits
__device__ __half g_wt [(size_t)NH * SEQ * SEQ];    // softmax weights
// fp16 transposed weights [N][K]
__device__ __half g_wqkv[(size_t)LDQKV * DM];
__device__ __half g_wo  [(size_t)DM * DM];
__device__ __half g_w1t [(size_t)DFF * DM];
__device__ __half g_w2t [(size_t)DM * DFF];

// ---------------- helpers ----------------
__device__ __forceinline__ float gelu_f(float x) {
    // 0.5x(1+tanh(z)) == x * sigmoid(2z),  2z = 1.5957691x + 0.07135482x^3
    float x3 = x * x * x;
    return x / (1.0f + __expf(-(1.5957691216057308f * x + 0.07135481627f * x3)));
}
__device__ __forceinline__ unsigned smem_u32(const void* p) {
    return (unsigned)__cvta_generic_to_shared(p);
}

#define CP_A16(saddr, gptr) \
    asm volatile("cp.async.cg.shared.global [%0], [%1], 16;\n" :: "r"(saddr), "l"(gptr))
#define CP_COMMIT() asm volatile("cp.async.commit_group;\n" ::: "memory")
#define CP_WAIT2()  asm volatile("cp.async.wait_group 2;\n" ::: "memory")
#define CP_WAIT0()  asm volatile("cp.async.wait_group 0;\n" ::: "memory")

#define LDSM4(r, addr) \
    asm volatile("ldmatrix.sync.aligned.m8n8.x4.shared.b16 {%0,%1,%2,%3}, [%4];" \
        : "=r"((r)[0]), "=r"((r)[1]), "=r"((r)[2]), "=r"((r)[3]) : "r"(addr))

__device__ __forceinline__ void mma16(float c[4], const uint32_t a[4], uint32_t b0, uint32_t b1) {
    asm volatile(
        "mma.sync.aligned.m16n8k16.row.col.f32.f16.f16.f32 "
        "{%0,%1,%2,%3},{%4,%5,%6,%7},{%8,%9},{%0,%1,%2,%3};"
        : "+f"(c[0]), "+f"(c[1]), "+f"(c[2]), "+f"(c[3])
        : "r"(a[0]), "r"(a[1]), "r"(a[2]), "r"(a[3]), "r"(b0), "r"(b1));
}

template <typename T> __device__ __forceinline__ void store2(T* p, float x, float y);
template <> __device__ __forceinline__ void store2<float>(float* p, float x, float y) {
    *(float2*)p = make_float2(x, y);
}
template <> __device__ __forceinline__ void store2<__half>(__half* p, float x, float y) {
    *(__half2*)p = __floats2half2_rn(x, y);
}

// ================= FP16 GEMM: C[M][N] = A[M][K] @ BT[N][K]^T =================
// block 128x128, 4 warps (2x2), warp 64x64, BK=32, 4-stage cp.async + ldmatrix
// EPI: 0 = store acc; 2 = store gelu(acc+bias); 3 = store acc+bias+addend
template <int EPI, typename OutT>
__global__ __launch_bounds__(128, 2)
void gemm16(const __half* __restrict__ A, const __half* __restrict__ BT,
            OutT* __restrict__ C, int K, int lda, int ldb, int ldc,
            long sAz, long sBz, long sCz,
            const float* __restrict__ bias, const float* __restrict__ addend,
            int causal) {
    extern __shared__ __half smh[];
    A  += (size_t)blockIdx.z * sAz;
    BT += (size_t)blockIdx.z * sBz;
    C  += (size_t)blockIdx.z * sCz;
    int m0 = blockIdx.y * BM, n0 = blockIdx.x * BN;
    int tid = threadIdx.x, warp = tid >> 5, lane = tid & 31;

    int kend = causal ? ((m0 + BM < K) ? (m0 + BM) : K) : K;
    int nk = kend / BK;

    uint32_t sb = smem_u32(smh);
    const __half* Ag = A + (size_t)(m0 + (tid >> 2)) * lda + (tid & 3) * 8;
    const __half* Bg = BT + (size_t)(n0 + (tid >> 2)) * ldb + (tid & 3) * 8;
    uint32_t Ad = sb + ((tid >> 2) * ROWH + (tid & 3) * 8) * 2;
    uint32_t Bd = sb + (A_H + (tid >> 2) * ROWH + (tid & 3) * 8) * 2;

    auto issue = [&](int t) {
        uint32_t off = (t & 3) * SLOT_B;
        int k0 = t * BK;
#pragma unroll
        for (int i = 0; i < 4; i++)
            CP_A16(Ad + off + i * 32 * ROWH * 2, Ag + (size_t)i * 32 * lda + k0);
#pragma unroll
        for (int i = 0; i < 4; i++)
            CP_A16(Bd + off + i * 32 * ROWH * 2, Bg + (size_t)i * 32 * ldb + k0);
    };

    issue(0); CP_COMMIT();
    if (nk > 1) issue(1);
    CP_COMMIT();
    if (nk > 2) issue(2);
    CP_COMMIT();

    int wm = (warp >> 1) * 64, wn = (warp & 1) * 64;
    uint32_t aAddr = sb + ((wm + (lane & 15)) * ROWH + (lane >> 4) * 8) * 2;
    uint32_t bAddr = sb + A_H * 2 +
                     ((wn + (lane & 7) + ((lane >> 4) & 1) * 8) * ROWH + ((lane >> 3) & 1) * 8) * 2;

    float acc[4][8][4];
#pragma unroll
    for (int i = 0; i < 4; i++)
#pragma unroll
        for (int j = 0; j < 8; j++)
#pragma unroll
            for (int q = 0; q < 4; q++) acc[i][j][q] = 0.f;

    for (int t = 0; t < nk; t++) {
        CP_WAIT2();
        __syncthreads();
        int u = t + 3;
        if (u < nk) issue(u);
        CP_COMMIT();

        uint32_t so = (t & 3) * SLOT_B;
#pragma unroll
        for (int ks = 0; ks < 2; ks++) {
            uint32_t a[4][4], b[4][4];
#pragma unroll
            for (int mt = 0; mt < 4; mt++)
                LDSM4(a[mt], aAddr + so + mt * (16 * ROWH * 2) + ks * 32);
#pragma unroll
            for (int p = 0; p < 4; p++)
                LDSM4(b[p], bAddr + so + p * (16 * ROWH * 2) + ks * 32);
#pragma unroll
            for (int mt = 0; mt < 4; mt++)
#pragma unroll
                for (int nt = 0; nt < 8; nt++)
                    mma16(acc[mt][nt], a[mt], b[nt >> 1][(nt & 1) * 2], b[nt >> 1][(nt & 1) * 2 + 1]);
        }
    }

    CP_WAIT0();
    __syncthreads();

    int r = lane >> 2, c2 = 2 * (lane & 3);
#pragma unroll
    for (int mt = 0; mt < 4; mt++)
#pragma unroll
        for (int nt = 0; nt < 8; nt++) {
            int gm0 = m0 + wm + mt * 16 + r;
            int gn = n0 + wn + nt * 8 + c2;
#pragma unroll
            for (int h = 0; h < 2; h++) {
                int gm = gm0 + h * 8;
                float vx = acc[mt][nt][h * 2], vy = acc[mt][nt][h * 2 + 1];
                if (EPI == 2 || EPI == 3) {
                    const float2 bb = *(const float2*)(bias + gn);
                    vx += bb.x; vy += bb.y;
                }
                if (EPI == 2) { vx = gelu_f(vx); vy = gelu_f(vy); }
                if (EPI == 3) {
                    const float2 ad = *(const float2*)(addend + (size_t)gm * ldc + gn);
                    vx += ad.x; vy += ad.y;
                }
                store2<OutT>(C + (size_t)gm * ldc + gn, vx, vy);
            }
        }
}

// ================= scores: logits = q k^T / 16 + ab (+causal mask), fp32 out =================
__global__ __launch_bounds__(128, 2)
void scores16(const __half* __restrict__ qkv, const float* __restrict__ ab,
              float* __restrict__ sc) {
    int h = blockIdx.z;
    int m0 = blockIdx.y * BM, n0 = blockIdx.x * BN;
    if (n0 > m0 + BM - 1) return;   // fully masked: softmax never reads here
    float* out = sc + ((size_t)h << 22);

    extern __shared__ __half smh[];
    int tid = threadIdx.x, warp = tid >> 5, lane = tid & 31;
    uint32_t sb = smem_u32(smh);

    const __half* Ag = qkv + (size_t)h * DH + (size_t)(m0 + (tid >> 2)) * LDQKV + (tid & 3) * 8;
    const __half* Bg = qkv + DM + (size_t)h * DH + (size_t)(n0 + (tid >> 2)) * LDQKV + (tid & 3) * 8;
    uint32_t Ad = sb + ((tid >> 2) * ROWH + (tid & 3) * 8) * 2;
    uint32_t Bd = sb + (A_H + (tid >> 2) * ROWH + (tid & 3) * 8) * 2;

    auto issue = [&](int t) {
        uint32_t off = (t & 3) * SLOT_B;
        int k0 = t * BK;
#pragma unroll
        for (int i = 0; i < 4; i++)
            CP_A16(Ad + off + i * 32 * ROWH * 2, Ag + (size_t)i * 32 * LDQKV + k0);
#pragma unroll
        for (int i = 0; i < 4; i++)
            CP_A16(Bd + off + i * 32 * ROWH * 2, Bg + (size_t)i * 32 * LDQKV + k0);
    };

    const int nk = DH / BK;   // 8
    issue(0); CP_COMMIT();
    issue(1); CP_COMMIT();
    issue(2); CP_COMMIT();

    int wm = (warp >> 1) * 64, wn = (warp & 1) * 64;
    uint32_t aAddr = sb + ((wm + (lane & 15)) * ROWH + (lane >> 4) * 8) * 2;
    uint32_t bAddr = sb + A_H * 2 +
                     ((wn + (lane & 7) + ((lane >> 4) & 1) * 8) * ROWH + ((lane >> 3) & 1) * 8) * 2;

    float acc[4][8][4];
#pragma unroll
    for (int i = 0; i < 4; i++)
#pragma unroll
        for (int j = 0; j < 8; j++)
#pragma unroll
            for (int q = 0; q < 4; q++) acc[i][j][q] = 0.f;

    for (int t = 0; t < nk; t++) {
        CP_WAIT2();
        __syncthreads();
        int u = t + 3;
        if (u < nk) issue(u);
        CP_COMMIT();
        uint32_t so = (t & 3) * SLOT_B;
#pragma unroll
        for (int ks = 0; ks < 2; ks++) {
            uint32_t a[4][4], b[4][4];
#pragma unroll
            for (int mt = 0; mt < 4; mt++)
                LDSM4(a[mt], aAddr + so + mt * (16 * ROWH * 2) + ks * 32);
#pragma unroll
            for (int p = 0; p < 4; p++)
                LDSM4(b[p], bAddr + so + p * (16 * ROWH * 2) + ks * 32);
#pragma unroll
            for (int mt = 0; mt < 4; mt++)
#pragma unroll
                for (int nt = 0; nt < 8; nt++)
                    mma16(acc[mt][nt], a[mt], b[nt >> 1][(nt & 1) * 2], b[nt >> 1][(nt & 1) * 2 + 1]);
        }
    }

    CP_WAIT0();
    __syncthreads();

    const float scale = 1.0f / 16.0f;
    int r = lane >> 2, c2 = 2 * (lane & 3);
#pragma unroll
    for (int mt = 0; mt < 4; mt++)
#pragma unroll
        for (int nt = 0; nt < 8; nt++) {
            int gm0 = m0 + wm + mt * 16 + r;
            int gn = n0 + wn + nt * 8 + c2;
#pragma unroll
            for (int hh = 0; hh < 2; hh++) {
                int gm = gm0 + hh * 8;
                size_t base = (size_t)gm * SEQ + gn;
                const float2 bb = *(const float2*)(ab + base);
                float vx = acc[mt][nt][hh * 2] * scale + bb.x + ((gn > gm) ? -1e10f : 0.f);
                float vy = acc[mt][nt][hh * 2 + 1] * scale + bb.y + ((gn + 1 > gm) ? -1e10f : 0.f);
                *(float2*)(out + base) = make_float2(vx, vy);
            }
        }
}

// ================= softmax over causal prefix; writes fp16 weights, zero-pads to 128-bdy =================
__global__ void softmax16(const float* __restrict__ sc, __half* __restrict__ wt) {
    int b = blockIdx.x;
    int h = b >> 11, t = b & 2047;
    const float* p = sc + ((size_t)h << 22) + (size_t)t * SEQ;
    __half* w = wt + ((size_t)h << 22) + (size_t)t * SEQ;
    int n = t + 1;
    int len = ((t >> 7) + 1) << 7;
    __shared__ float red[256];
    int tid = threadIdx.x;

    float vals[8];
    float m = -3.4e38f;
#pragma unroll
    for (int i = 0; i < 8; i++) {
        int j = tid + i * 256;
        vals[i] = (j < n) ? p[j] : -3.4e38f;
        m = fmaxf(m, vals[i]);
    }
    red[tid] = m; __syncthreads();
    for (int s = 128; s > 0; s >>= 1) { if (tid < s) red[tid] = fmaxf(red[tid], red[tid + s]); __syncthreads(); }
    m = red[0]; __syncthreads();

    float sum = 0.f;
#pragma unroll
    for (int i = 0; i < 8; i++) {
        int j = tid + i * 256;
        if (j < n) { vals[i] = __expf(vals[i] - m); sum += vals[i]; }
    }
    red[tid] = sum; __syncthreads();
    for (int s = 128; s > 0; s >>= 1) { if (tid < s) red[tid] += red[tid + s]; __syncthreads(); }
    float inv = 1.0f / red[0];
#pragma unroll
    for (int i = 0; i < 8; i++) {
        int j = tid + i * 256;
        if (j < n)        w[j] = __float2half(vals[i] * inv);
        else if (j < len) w[j] = __float2half(0.f);
    }
}

// ================= weight transpose + fp32->fp16: dst[n][k] = src[k][n] =================
__global__ void trw(const float* __restrict__ src, __half* __restrict__ dst, int K, int N) {
    __shared__ float tile[32][33];
    int k0 = blockIdx.y * 32, n0 = blockIdx.x * 32;
    int tx = threadIdx.x, ty = threadIdx.y;
#pragma unroll
    for (int i = 0; i < 4; i++)
        tile[ty + i * 8][tx] = src[(size_t)(k0 + ty + i * 8) * N + n0 + tx];
    __syncthreads();
#pragma unroll
    for (int i = 0; i < 4; i++)
        dst[(size_t)(n0 + ty + i * 8) * K + k0 + tx] = __float2half(tile[tx][ty + i * 8]);
}

// ================= v transpose (half): vt[c][T] = qkv[T][2*DM + c] =================
__global__ void trv(const __half* __restrict__ qkv, __half* __restrict__ vt) {
    __shared__ __half tile[32][33];
    int c0 = blockIdx.x * 32, T0 = blockIdx.y * 32;
    int tx = threadIdx.x, ty = threadIdx.y;
#pragma unroll
    for (int i = 0; i < 4; i++)
        tile[ty + i * 8][tx] = qkv[(size_t)(T0 + ty + i * 8) * LDQKV + 2 * DM + c0 + tx];
    __syncthreads();
#pragma unroll
    for (int i = 0; i < 4; i++)
        vt[(size_t)(c0 + ty + i * 8) * SEQ + T0 + tx] = tile[tx][ty + i * 8];
}

// ================= layernorm -> half =================
__global__ void ln_kernel(const float* __restrict__ x, const float* __restrict__ sc,
                          const float* __restrict__ of, __half* __restrict__ xn) {
    int row = blockIdx.x;
    const float* xr = x + (size_t)row * DM;
    __half* xo = xn + (size_t)row * DM;
    __shared__ float red[256];
    int tid = threadIdx.x;
    float s = 0.f;
    for (int j = tid; j < DM; j += 256) s += xr[j];
    red[tid] = s; __syncthreads();
    for (int st = 128; st > 0; st >>= 1) { if (tid < st) red[tid] += red[tid + st]; __syncthreads(); }
    float mean = red[0] * (1.0f / DM);
    __syncthreads();
    float v = 0.f;
    for (int j = tid; j < DM; j += 256) { float d = xr[j] - mean; v += d * d; }
    red[tid] = v; __syncthreads();
    for (int st = 128; st > 0; st >>= 1) { if (tid < st) red[tid] += red[tid + st]; __syncthreads(); }
    float rstd = rsqrtf(red[0] * (1.0f / DM) + 1e-5f);
    for (int j = tid; j < DM; j += 256)
        xo[j] = __float2half(sc[j] * rstd * (xr[j] - mean) + of[j]);
}

// ================= RoPE on half q,k =================
__global__ void rope_kernel(__half* __restrict__ qkv) {
    int t = blockIdx.x, tid = threadIdx.x;
    __shared__ float ss[32], cc[32];
    if (tid < 32) {
        double inv = pow(10000.0, -((double)(2 * tid)) / 64.0);
        double a = (double)t * inv;
        ss[tid] = (float)sin(a); cc[tid] = (float)cos(a);
    }
    __syncthreads();
    int head = tid >> 5, i = tid & 31;
    float s = ss[i], co = cc[i];
    size_t qoff = (size_t)t * LDQKV + head * DH + 2 * i;
    size_t koff = qoff + DM;
    float q0 = __half2float(qkv[qoff]), q1 = __half2float(qkv[qoff + 1]);
    qkv[qoff]     = __float2half(q0 * co - q1 * s);
    qkv[qoff + 1] = __float2half(q1 * co + q0 * s);
    float k0 = __half2float(qkv[koff]), k1 = __half2float(qkv[koff + 1]);
    qkv[koff]     = __float2half(k0 * co - k1 * s);
    qkv[koff + 1] = __float2half(k1 * co + k0 * s);
}

// ================= launch =================
extern "C" void kernel_launch(void* const* d_in, const int* in_sizes, int n_in,
                              void* d_out, int out_size) {
    const float* x   = (const float*)d_in[0];
    const float* ab  = (const float*)d_in[1];
    const float* lns = (const float*)d_in[2];
    const float* lno = (const float*)d_in[3];
    const float* wq  = (const float*)d_in[4];
    const float* wk  = (const float*)d_in[5];
    const float* wv  = (const float*)d_in[6];
    const float* wo  = (const float*)d_in[7];
    const float* w1  = (const float*)d_in[8];
    const float* b1  = (const float*)d_in[9];
    const float* w2  = (const float*)d_in[10];
    const float* b2  = (const float*)d_in[11];
    float* out = (float*)d_out;

    __half *xn, *qkv, *vt, *av, *f1, *wt, *wqkv16, *wo16, *w1t16, *w2t16;
    float *ao, *scr;
    cudaGetSymbolAddress((void**)&xn,     g_xn);
    cudaGetSymbolAddress((void**)&qkv,    g_qkv);
    cudaGetSymbolAddress((void**)&vt,     g_vt);
    cudaGetSymbolAddress((void**)&av,     g_av);
    cudaGetSymbolAddress((void**)&ao,     g_ao);
    cudaGetSymbolAddress((void**)&f1,     g_f1);
    cudaGetSymbolAddress((void**)&scr,    g_sc);
    cudaGetSymbolAddress((void**)&wt,     g_wt);
    cudaGetSymbolAddress((void**)&wqkv16, g_wqkv);
    cudaGetSymbolAddress((void**)&wo16,   g_wo);
    cudaGetSymbolAddress((void**)&w1t16,  g_w1t);
    cudaGetSymbolAddress((void**)&w2t16,  g_w2t);

    cudaFuncSetAttribute(gemm16<0, __half>, cudaFuncAttributeMaxDynamicSharedMemorySize, SMEM_B);
    cudaFuncSetAttribute(gemm16<0, float>,  cudaFuncAttributeMaxDynamicSharedMemorySize, SMEM_B);
    cudaFuncSetAttribute(gemm16<2, __half>, cudaFuncAttributeMaxDynamicSharedMemorySize, SMEM_B);
    cudaFuncSetAttribute(gemm16<3, float>,  cudaFuncAttributeMaxDynamicSharedMemorySize, SMEM_B);
    cudaFuncSetAttribute(scores16,          cudaFuncAttributeMaxDynamicSharedMemorySize, SMEM_B);

    dim3 tb(32, 8);
    // 0. weights: transpose + convert to fp16 [N][K]
    trw<<<dim3(DM / 32, DM / 32), tb>>>(wq, wqkv16, DM, DM);
    trw<<<dim3(DM / 32, DM / 32), tb>>>(wk, wqkv16 + (size_t)DM * DM, DM, DM);
    trw<<<dim3(DM / 32, DM / 32), tb>>>(wv, wqkv16 + (size_t)2 * DM * DM, DM, DM);
    trw<<<dim3(DM / 32, DM / 32), tb>>>(wo, wo16, DM, DM);
    trw<<<dim3(DFF / 32, DM / 32), tb>>>(w1, w1t16, DM, DFF);
    trw<<<dim3(DM / 32, DFF / 32), tb>>>(w2, w2t16, DFF, DM);

    // 1. LayerNorm -> half
    ln_kernel<<<SEQ, 256>>>(x, lns, lno, xn);

    // 2. fused QKV: [2048 x 12288]
    gemm16<0, __half><<<dim3(LDQKV / BN, SEQ / BM), 128, SMEM_B>>>(
        xn, wqkv16, qkv, DM, DM, DM, LDQKV, 0, 0, 0, nullptr, nullptr, 0);

    // 3. RoPE
    rope_kernel<<<SEQ, 512>>>(qkv);

    // 4. v^T for AV B-operand
    trv<<<dim3(DM / 32, SEQ / 32), tb>>>(qkv, vt);

    // 5. scores (masked blocks skipped)
    scores16<<<dim3(SEQ / BN, SEQ / BM, NH), 128, SMEM_B>>>(qkv, ab, scr);

    // 6. softmax -> fp16 weights (+ zero pad to 128-boundary)
    softmax16<<<NH * SEQ, 256>>>(scr, wt);

    // 7. attn_vec = weights @ v  (causal K-bound), half out
    gemm16<0, __half><<<dim3(DH / BN, SEQ / BM, NH), 128, SMEM_B>>>(
        wt, vt, av, SEQ, SEQ, SEQ, DM,
        (long)SEQ * SEQ, (long)DH * SEQ, (long)DH, nullptr, nullptr, 1);

    // 8. attn_out = av @ wo, fp32
    gemm16<0, float><<<dim3(DM / BN, SEQ / BM), 128, SMEM_B>>>(
        av, wo16, ao, DM, DM, DM, DM, 0, 0, 0, nullptr, nullptr, 0);

    // 9. f1 = gelu(xn @ w1 + b1), half
    gemm16<2, __half><<<dim3(DFF / BN, SEQ / BM), 128, SMEM_B>>>(
        xn, w1t16, f1, DM, DM, DM, DFF, 0, 0, 0, b1, nullptr, 0);

    // 10. out = f1 @ w2 + b2 + ao, fp32
    gemm16<3, float><<<dim3(DM / BN, SEQ / BM), 128, SMEM_B>>>(
        f1, w2t16, out, DFF, DFF, DFF, DM, 0, 0, 0, b2, ao, 0);
}